// round 7
// baseline (speedup 1.0000x reference)
#include <cuda_runtime.h>
#include <cstddef>

#define BB 2048
#define TT 1024
#define DD 64
#define HH 32

typedef unsigned long long u64;

// 768 MB scratch for precomputed layer-0 input gates: [row][t][96]
__device__ float g_gx[(size_t)BB * TT * 96];

// ---- packed fp32x2 helpers (sm_100+) ----
__device__ __forceinline__ u64 ffma2(u64 a, u64 b, u64 c) {
    u64 d;
    asm("fma.rn.f32x2 %0, %1, %2, %3;" : "=l"(d) : "l"(a), "l"(b), "l"(c));
    return d;
}
__device__ __forceinline__ u64 pack2(float lo, float hi) {
    u64 r;
    asm("mov.b64 %0, {%1, %2};" : "=l"(r) : "f"(lo), "f"(hi));
    return r;
}
__device__ __forceinline__ float sum2(u64 v) {
    float a, b;
    asm("mov.b64 {%0, %1}, %2;" : "=f"(a), "=f"(b) : "l"(v));
    return a + b;
}
__device__ __forceinline__ float fast_sigmoid(float x) {
    float e;
    asm("ex2.approx.f32 %0, %1;" : "=f"(e) : "f"(-1.4426950408889634f * x));
    float r;
    asm("rcp.approx.f32 %0, %1;" : "=f"(r) : "f"(1.0f + e));
    return r;
}
__device__ __forceinline__ float fast_tanh(float x) {
    return fmaf(2.0f, fast_sigmoid(2.0f * x), -1.0f);
}

// ==================== Phase 1: gx = x @ W_ih0^T + b_ih0 ====================
// One block per batch row; 16 batches of 64 tokens; 8 warps x 8 tokens each.
__global__ void __launch_bounds__(256, 1)
gx_kernel(const float* __restrict__ x,
          const float* __restrict__ wih0, const float* __restrict__ bih0)
{
    __shared__ float4 w4[16 * 96];    // [kk<16][gate<96] transposed weights, 24KB
    __shared__ float4 xs[64 * 16];    // 64 tokens x 64 floats, 16KB

    const int tid  = threadIdx.x;
    const int warp = tid >> 5;
    const int lane = tid & 31;

    for (int idx = tid; idx < 1536; idx += 256) {
        int g = idx % 96, kk = idx / 96;
        w4[kk * 96 + g] = *(const float4*)(wih0 + g * 64 + kk * 4);
    }
    const float b0 = bih0[lane], b1 = bih0[32 + lane], b2 = bih0[64 + lane];

    const float4* xrow = (const float4*)(x + (size_t)blockIdx.x * TT * DD);
    float* grow = g_gx + (size_t)blockIdx.x * TT * 96;

    for (int batch = 0; batch < 16; batch++) {
        __syncthreads();
        for (int i = tid; i < 1024; i += 256) xs[i] = xrow[batch * 1024 + i];
        __syncthreads();

        u64 a0[8], a1[8], a2[8];
#pragma unroll
        for (int tk = 0; tk < 8; tk++) {
            a0[tk] = pack2(b0, 0.f); a1[tk] = pack2(b1, 0.f); a2[tk] = pack2(b2, 0.f);
        }
        const float4* xw = xs + warp * 128;   // this warp's 8 tokens
#pragma unroll 4
        for (int kk = 0; kk < 16; kk++) {
            ulonglong2 wr = *(const ulonglong2*)(w4 + kk * 96 + lane);
            ulonglong2 wz = *(const ulonglong2*)(w4 + kk * 96 + 32 + lane);
            ulonglong2 wn = *(const ulonglong2*)(w4 + kk * 96 + 64 + lane);
#pragma unroll
            for (int tk = 0; tk < 8; tk++) {
                ulonglong2 xv = *(const ulonglong2*)(xw + tk * 16 + kk);
                a0[tk] = ffma2(wr.x, xv.x, a0[tk]); a0[tk] = ffma2(wr.y, xv.y, a0[tk]);
                a1[tk] = ffma2(wz.x, xv.x, a1[tk]); a1[tk] = ffma2(wz.y, xv.y, a1[tk]);
                a2[tk] = ffma2(wn.x, xv.x, a2[tk]); a2[tk] = ffma2(wn.y, xv.y, a2[tk]);
            }
        }
#pragma unroll
        for (int tk = 0; tk < 8; tk++) {
            float* o = grow + (size_t)(batch * 64 + warp * 8 + tk) * 96;
            o[lane]      = sum2(a0[tk]);
            o[32 + lane] = sum2(a1[tk]);
            o[64 + lane] = sum2(a2[tk]);
        }
    }
}

// ==================== Phase 2: recurrence, warp-independent ====================
// 128 blocks x 8 warps, 2 rows/warp. No block syncs in the loop.
__global__ void __launch_bounds__(256, 1)
gru2_kernel(const float* __restrict__ whh0, const float* __restrict__ bhh0,
            const float* __restrict__ wih1, const float* __restrict__ bih1,
            const float* __restrict__ whh1, const float* __restrict__ bhh1,
            const float* __restrict__ wcls, const float* __restrict__ bcls,
            float* __restrict__ out)
{
    __shared__ float4 w4hh1[8 * 96];   // [kk<8][gate<96], 12KB
    __shared__ float  h0s[16 * 32];    // per-warp-private h0 (2 rows each)
    __shared__ float  h1s[16 * 32];

    const int tid  = threadIdx.x;
    const int warp = tid >> 5;
    const int lane = tid & 31;

    for (int idx = tid; idx < 768; idx += 256) {
        int g = idx % 96, kk = idx / 96;
        w4hh1[kk * 96 + g] = *(const float4*)(whh1 + g * 32 + kk * 4);
    }
    for (int i = tid; i < 512; i += 256) { h0s[i] = 0.f; h1s[i] = 0.f; }

    // Register-resident W_hh0 and W_ih1: lane j holds gate rows j, 32+j, 64+j.
    u64 h0r_w[16], h0z_w[16], h0n_w[16];
    u64 i1r_w[16], i1z_w[16], i1n_w[16];
#pragma unroll
    for (int i = 0; i < 8; i++) {
        ulonglong2 a = *(const ulonglong2*)(whh0 + lane * 32 + i * 4);
        ulonglong2 b = *(const ulonglong2*)(whh0 + (32 + lane) * 32 + i * 4);
        ulonglong2 c = *(const ulonglong2*)(whh0 + (64 + lane) * 32 + i * 4);
        h0r_w[2 * i] = a.x; h0r_w[2 * i + 1] = a.y;
        h0z_w[2 * i] = b.x; h0z_w[2 * i + 1] = b.y;
        h0n_w[2 * i] = c.x; h0n_w[2 * i + 1] = c.y;
        ulonglong2 d = *(const ulonglong2*)(wih1 + lane * 32 + i * 4);
        ulonglong2 e = *(const ulonglong2*)(wih1 + (32 + lane) * 32 + i * 4);
        ulonglong2 f = *(const ulonglong2*)(wih1 + (64 + lane) * 32 + i * 4);
        i1r_w[2 * i] = d.x; i1r_w[2 * i + 1] = d.y;
        i1z_w[2 * i] = e.x; i1z_w[2 * i + 1] = e.y;
        i1n_w[2 * i] = f.x; i1n_w[2 * i + 1] = f.y;
    }
    const float bA  = bhh0[lane], bZ  = bhh0[32 + lane], bN  = bhh0[64 + lane];
    const float b1r = bih1[lane], b1z = bih1[32 + lane], b1n = bih1[64 + lane];
    const float bhr = bhh1[lane], bhz = bhh1[32 + lane], bhn = bhh1[64 + lane];

    const int r0 = blockIdx.x * 16 + warp * 2;    // global rows r0, r0+1
    float h0a = 0.f, h0b = 0.f, h1a = 0.f, h1b = 0.f;
    float* h0w = h0s + warp * 64;
    float* h1w = h1s + warp * 64;

    const float* gxa = g_gx + (size_t)r0 * TT * 96;
    const float* gxb = gxa + (size_t)TT * 96;
    // preload gx(0)
    float ga_r = gxa[lane], ga_z = gxa[32 + lane], ga_n = gxa[64 + lane];
    float gb_r = gxb[lane], gb_z = gxb[32 + lane], gb_n = gxb[64 + lane];
    gxa += 96; gxb += 96;

    __syncthreads();   // weights + h zeros visible

    for (int t = 0; t < TT; t++) {
        // ---- consume gx(t): fold r,z parts into L0 acc init; keep n part scalar ----
        u64 gr0 = pack2(ga_r + bA, 0.f), gz0 = pack2(ga_z + bZ, 0.f), gn0 = pack2(bN, 0.f);
        u64 gr1 = pack2(gb_r + bA, 0.f), gz1 = pack2(gb_z + bZ, 0.f), gn1 = pack2(bN, 0.f);
        const float xnA = ga_n, xnB = gb_n;

        // ---- prefetch gx(t+1) (consumed at top of next step) ----
        if (t + 1 < TT) {
            ga_r = gxa[lane]; ga_z = gxa[32 + lane]; ga_n = gxa[64 + lane];
            gb_r = gxb[lane]; gb_z = gxb[32 + lane]; gb_n = gxb[64 + lane];
            gxa += 96; gxb += 96;
        }

        // ---- L1 hidden gemm (smem W_hh1, reads h1(t-1)) — independent, issue first ----
        u64 dr0 = pack2(bhr, 0.f), dz0 = pack2(bhz, 0.f), dn0 = pack2(bhn, 0.f);
        u64 dr1 = dr0, dz1 = dz0, dn1 = dn0;
#pragma unroll
        for (int kk = 0; kk < 8; kk++) {
            ulonglong2 hr = *(const ulonglong2*)(w4hh1 + kk * 96 + lane);
            ulonglong2 hz = *(const ulonglong2*)(w4hh1 + kk * 96 + 32 + lane);
            ulonglong2 hn = *(const ulonglong2*)(w4hh1 + kk * 96 + 64 + lane);
            ulonglong2 va = *(const ulonglong2*)(h1w + kk * 4);
            ulonglong2 vb = *(const ulonglong2*)(h1w + 32 + kk * 4);
            dr0 = ffma2(hr.x, va.x, dr0); dr0 = ffma2(hr.y, va.y, dr0);
            dz0 = ffma2(hz.x, va.x, dz0); dz0 = ffma2(hz.y, va.y, dz0);
            dn0 = ffma2(hn.x, va.x, dn0); dn0 = ffma2(hn.y, va.y, dn0);
            dr1 = ffma2(hr.x, vb.x, dr1); dr1 = ffma2(hr.y, vb.y, dr1);
            dz1 = ffma2(hz.x, vb.x, dz1); dz1 = ffma2(hz.y, vb.y, dz1);
            dn1 = ffma2(hn.x, vb.x, dn1); dn1 = ffma2(hn.y, vb.y, dn1);
        }

        // ---- L0 hidden gemm (register W_hh0, reads h0(t-1)) ----
#pragma unroll
        for (int kk = 0; kk < 8; kk++) {
            ulonglong2 va = *(const ulonglong2*)(h0w + kk * 4);
            ulonglong2 vb = *(const ulonglong2*)(h0w + 32 + kk * 4);
            gr0 = ffma2(h0r_w[2 * kk], va.x, gr0); gr0 = ffma2(h0r_w[2 * kk + 1], va.y, gr0);
            gz0 = ffma2(h0z_w[2 * kk], va.x, gz0); gz0 = ffma2(h0z_w[2 * kk + 1], va.y, gz0);
            gn0 = ffma2(h0n_w[2 * kk], va.x, gn0); gn0 = ffma2(h0n_w[2 * kk + 1], va.y, gn0);
            gr1 = ffma2(h0r_w[2 * kk], vb.x, gr1); gr1 = ffma2(h0r_w[2 * kk + 1], vb.y, gr1);
            gz1 = ffma2(h0z_w[2 * kk], vb.x, gz1); gz1 = ffma2(h0z_w[2 * kk + 1], vb.y, gz1);
            gn1 = ffma2(h0n_w[2 * kk], vb.x, gn1); gn1 = ffma2(h0n_w[2 * kk + 1], vb.y, gn1);
        }
        // ---- layer-0 activations (torch GRU: b_hh_n inside r*) ----
        {
            float rA = fast_sigmoid(sum2(gr0));
            float zA = fast_sigmoid(sum2(gz0));
            float nA = fast_tanh(xnA + rA * sum2(gn0));
            h0a = nA + zA * (h0a - nA);
            float rB = fast_sigmoid(sum2(gr1));
            float zB = fast_sigmoid(sum2(gz1));
            float nB = fast_tanh(xnB + rB * sum2(gn1));
            h0b = nB + zB * (h0b - nB);
        }
        __syncwarp();
        h0w[lane] = h0a; h0w[32 + lane] = h0b;
        __syncwarp();

        // ---- L1 input gemm (register W_ih1, reads new h0) ----
        u64 cr0 = pack2(b1r, 0.f), cz0 = pack2(b1z, 0.f), cn0 = pack2(b1n, 0.f);
        u64 cr1 = cr0, cz1 = cz0, cn1 = cn0;
#pragma unroll
        for (int kk = 0; kk < 8; kk++) {
            ulonglong2 va = *(const ulonglong2*)(h0w + kk * 4);
            ulonglong2 vb = *(const ulonglong2*)(h0w + 32 + kk * 4);
            cr0 = ffma2(i1r_w[2 * kk], va.x, cr0); cr0 = ffma2(i1r_w[2 * kk + 1], va.y, cr0);
            cz0 = ffma2(i1z_w[2 * kk], va.x, cz0); cz0 = ffma2(i1z_w[2 * kk + 1], va.y, cz0);
            cn0 = ffma2(i1n_w[2 * kk], va.x, cn0); cn0 = ffma2(i1n_w[2 * kk + 1], va.y, cn0);
            cr1 = ffma2(i1r_w[2 * kk], vb.x, cr1); cr1 = ffma2(i1r_w[2 * kk + 1], vb.y, cr1);
            cz1 = ffma2(i1z_w[2 * kk], vb.x, cz1); cz1 = ffma2(i1z_w[2 * kk + 1], vb.y, cz1);
            cn1 = ffma2(i1n_w[2 * kk], vb.x, cn1); cn1 = ffma2(i1n_w[2 * kk + 1], vb.y, cn1);
        }
        // ---- layer-1 activations ----
        {
            float rA = fast_sigmoid(sum2(cr0) + sum2(dr0));
            float zA = fast_sigmoid(sum2(cz0) + sum2(dz0));
            float nA = fast_tanh(sum2(cn0) + rA * sum2(dn0));
            h1a = nA + zA * (h1a - nA);
            float rB = fast_sigmoid(sum2(cr1) + sum2(dr1));
            float zB = fast_sigmoid(sum2(cz1) + sum2(dz1));
            float nB = fast_tanh(sum2(cn1) + rB * sum2(dn1));
            h1b = nB + zB * (h1b - nB);
        }
        __syncwarp();
        h1w[lane] = h1a; h1w[32 + lane] = h1b;
        __syncwarp();
    }

    // ---- outputs: y [B], hidden [2,B,H] ----
    const float wc = wcls[lane];
    const float bc = bcls[0];
    out[BB + (r0)     * HH + lane] = h0a;
    out[BB + (r0 + 1) * HH + lane] = h0b;
    out[BB + BB * HH + (r0)     * HH + lane] = h1a;
    out[BB + BB * HH + (r0 + 1) * HH + lane] = h1b;
    float pA = h1a * wc, pB = h1b * wc;
#pragma unroll
    for (int off = 16; off; off >>= 1) {
        pA += __shfl_xor_sync(0xffffffffu, pA, off);
        pB += __shfl_xor_sync(0xffffffffu, pB, off);
    }
    if (lane == 0) { out[r0] = fast_sigmoid(pA + bc); out[r0 + 1] = fast_sigmoid(pB + bc); }
}

extern "C" void kernel_launch(void* const* d_in, const int* in_sizes, int n_in,
                              void* d_out, int out_size) {
    (void)in_sizes; (void)n_in; (void)out_size;
    const float* x    = (const float*)d_in[0];
    const float* wih0 = (const float*)d_in[1];
    const float* whh0 = (const float*)d_in[2];
    const float* bih0 = (const float*)d_in[3];
    const float* bhh0 = (const float*)d_in[4];
    const float* wih1 = (const float*)d_in[5];
    const float* whh1 = (const float*)d_in[6];
    const float* bih1 = (const float*)d_in[7];
    const float* bhh1 = (const float*)d_in[8];
    const float* wcls = (const float*)d_in[9];
    const float* bcls = (const float*)d_in[10];
    float* out = (float*)d_out;

    gx_kernel<<<BB, 256>>>(x, wih0, bih0);
    gru2_kernel<<<128, 256>>>(whh0, bhh0, wih1, bih1, whh1, bhh1, wcls, bcls, out);
}

// round 8
// speedup vs baseline: 1.0825x; 1.0825x over previous
#include <cuda_runtime.h>
#include <cstddef>

#define BB 2048
#define TT 1024
#define DD 64
#define HH 32

typedef unsigned long long u64;

// ---- packed fp32x2 helpers (sm_100+) ----
__device__ __forceinline__ u64 ffma2(u64 a, u64 b, u64 c) {
    u64 d;
    asm("fma.rn.f32x2 %0, %1, %2, %3;" : "=l"(d) : "l"(a), "l"(b), "l"(c));
    return d;
}
__device__ __forceinline__ u64 pack2(float lo, float hi) {
    u64 r;
    asm("mov.b64 %0, {%1, %2};" : "=l"(r) : "f"(lo), "f"(hi));
    return r;
}
__device__ __forceinline__ float sum2(u64 v) {
    float a, b;
    asm("mov.b64 {%0, %1}, %2;" : "=f"(a), "=f"(b) : "l"(v));
    return a + b;
}
__device__ __forceinline__ float fast_sigmoid(float x) {
    float e;
    asm("ex2.approx.f32 %0, %1;" : "=f"(e) : "f"(-1.4426950408889634f * x));
    float r;
    asm("rcp.approx.f32 %0, %1;" : "=f"(r) : "f"(1.0f + e));
    return r;
}
__device__ __forceinline__ float fast_tanh(float x) {
    return fmaf(2.0f, fast_sigmoid(2.0f * x), -1.0f);
}

#define BAR() asm volatile("bar.sync 0, 384;" ::: "memory")

// layer-0 input gemm, half-K (32), 8 rows, register weights
__device__ __forceinline__ void gx_gemm(const u64* __restrict__ pwr,
                                        const u64* __restrict__ pwz,
                                        const u64* __restrict__ pwn,
                                        const float4* __restrict__ xsw,
                                        float* __restrict__ gout,
                                        int lane, float b_r, float b_z, float b_n) {
    u64 ar[8], az[8], an[8];
#pragma unroll
    for (int r = 0; r < 8; r++) {
        ar[r] = pack2(b_r, 0.f); az[r] = pack2(b_z, 0.f); an[r] = pack2(b_n, 0.f);
    }
#pragma unroll
    for (int kk = 0; kk < 8; kk++) {
#pragma unroll
        for (int r = 0; r < 8; r++) {
            ulonglong2 xv = *(const ulonglong2*)(xsw + r * 8 + kk);
            ar[r] = ffma2(pwr[2 * kk], xv.x, ar[r]); ar[r] = ffma2(pwr[2 * kk + 1], xv.y, ar[r]);
            az[r] = ffma2(pwz[2 * kk], xv.x, az[r]); az[r] = ffma2(pwz[2 * kk + 1], xv.y, az[r]);
            an[r] = ffma2(pwn[2 * kk], xv.x, an[r]); an[r] = ffma2(pwn[2 * kk + 1], xv.y, an[r]);
        }
    }
#pragma unroll
    for (int r = 0; r < 8; r++) {
        gout[r * 96 + lane]      = sum2(ar[r]);
        gout[r * 96 + 32 + lane] = sum2(az[r]);
        gout[r * 96 + 64 + lane] = sum2(an[r]);
    }
}

__global__ void __launch_bounds__(384, 1)
gru2_kernel(const float* __restrict__ x,
            const float* __restrict__ wih0, const float* __restrict__ whh0,
            const float* __restrict__ bih0, const float* __restrict__ bhh0,
            const float* __restrict__ wih1, const float* __restrict__ whh1,
            const float* __restrict__ bih1, const float* __restrict__ bhh1,
            const float* __restrict__ wcls, const float* __restrict__ bcls,
            float* __restrict__ out)
{
    extern __shared__ float smf[];
    float4* w4hh1  = (float4*)smf;             // [8][96] f4      = 12KB
    float*  gxs    = smf + 3072;               // [2][2][16][96]  = 24KB
    float*  h0ring = smf + 9216;               // [2][16][32]     = 4KB
    float*  h1ring = smf + 10240;              // [2][16][32]     = 4KB
    float4* xs     = (float4*)(smf + 11264);   // [4][8][8] f4    = 4KB

    const int tid  = threadIdx.x;
    const int warp = tid >> 5;
    const int lane = tid & 31;
    const int rowbase16 = blockIdx.x * 16;

    // cooperative init (all 384 threads): transpose W_hh1, zero h rings
    for (int idx = tid; idx < 768; idx += 384) {
        int g = idx % 96, kk = idx / 96;
        w4hh1[kk * 96 + g] = *(const float4*)(whh1 + g * 32 + kk * 4);
    }
    for (int i = tid; i < 2048; i += 384) h0ring[i] = 0.f;   // h0ring+h1ring contiguous

    if (warp < 4) {
        // ============ L0 warps: h0 recurrence, 4 rows, W_hh0 in registers ============
        u64 wr[16], wz[16], wn[16];
#pragma unroll
        for (int i = 0; i < 8; i++) {
            ulonglong2 a = *(const ulonglong2*)(whh0 + lane * 32 + i * 4);
            ulonglong2 b = *(const ulonglong2*)(whh0 + (32 + lane) * 32 + i * 4);
            ulonglong2 c = *(const ulonglong2*)(whh0 + (64 + lane) * 32 + i * 4);
            wr[2 * i] = a.x; wr[2 * i + 1] = a.y;
            wz[2 * i] = b.x; wz[2 * i + 1] = b.y;
            wn[2 * i] = c.x; wn[2 * i + 1] = c.y;
        }
        const float bR = bhh0[lane], bZ = bhh0[32 + lane], bN = bhh0[64 + lane];
        const int rb = warp * 4;
        float h0r[4] = {0.f, 0.f, 0.f, 0.f};

        BAR();   // gx(0), zeros, shared weights visible

        for (int i = 0; i <= TT; i++) {
            if (i < TT) {
                const float* g0 = gxs + (i & 1) * 3072 + rb * 96;
                const float* g1 = g0 + 1536;
                const float* hp = h0ring + ((i + 1) & 1) * 512 + rb * 32;   // h0(i-1)
                u64 gr[4], gz[4], gn[4];
#pragma unroll
                for (int r = 0; r < 4; r++) {
                    gr[r] = pack2(bR, 0.f); gz[r] = pack2(bZ, 0.f); gn[r] = pack2(bN, 0.f);
                }
#pragma unroll
                for (int kk = 0; kk < 8; kk++) {
#pragma unroll
                    for (int r = 0; r < 4; r++) {
                        ulonglong2 hv = *(const ulonglong2*)(hp + r * 32 + kk * 4);
                        gr[r] = ffma2(wr[2 * kk], hv.x, gr[r]); gr[r] = ffma2(wr[2 * kk + 1], hv.y, gr[r]);
                        gz[r] = ffma2(wz[2 * kk], hv.x, gz[r]); gz[r] = ffma2(wz[2 * kk + 1], hv.y, gz[r]);
                        gn[r] = ffma2(wn[2 * kk], hv.x, gn[r]); gn[r] = ffma2(wn[2 * kk + 1], hv.y, gn[r]);
                    }
                }
                float* hw = h0ring + (i & 1) * 512 + rb * 32;
#pragma unroll
                for (int r = 0; r < 4; r++) {
                    float xr = g0[r * 96 + lane]      + g1[r * 96 + lane];
                    float xz = g0[r * 96 + 32 + lane] + g1[r * 96 + 32 + lane];
                    float xn = g0[r * 96 + 64 + lane] + g1[r * 96 + 64 + lane];
                    float rg = fast_sigmoid(xr + sum2(gr[r]));
                    float zg = fast_sigmoid(xz + sum2(gz[r]));
                    float ng = fast_tanh(xn + rg * sum2(gn[r]));   // b_hh_n inside r* (torch)
                    h0r[r] = ng + zg * (h0r[r] - ng);
                    hw[r * 32 + lane] = h0r[r];
                }
            }
            BAR();
        }
#pragma unroll
        for (int r = 0; r < 4; r++)
            out[BB + (rowbase16 + rb + r) * HH + lane] = h0r[r];

    } else if (warp < 8) {
        // ============ L1 warps: h1 recurrence one step behind, W_ih1 in registers ============
        u64 iwr[16], iwz[16], iwn[16];
#pragma unroll
        for (int i = 0; i < 8; i++) {
            ulonglong2 a = *(const ulonglong2*)(wih1 + lane * 32 + i * 4);
            ulonglong2 b = *(const ulonglong2*)(wih1 + (32 + lane) * 32 + i * 4);
            ulonglong2 c = *(const ulonglong2*)(wih1 + (64 + lane) * 32 + i * 4);
            iwr[2 * i] = a.x; iwr[2 * i + 1] = a.y;
            iwz[2 * i] = b.x; iwz[2 * i + 1] = b.y;
            iwn[2 * i] = c.x; iwn[2 * i + 1] = c.y;
        }
        const float biR = bih1[lane], biZ = bih1[32 + lane], biN = bih1[64 + lane];
        const float bhR = bhh1[lane], bhZ = bhh1[32 + lane], bhN = bhh1[64 + lane];
        const float wc = wcls[lane];
        const float bc = bcls[0];
        const int rb = (warp - 4) * 4;
        float h1r[4] = {0.f, 0.f, 0.f, 0.f};

        BAR();

        for (int i = 0; i <= TT; i++) {
            if (i >= 1) {
                const int j = i - 1;                                   // computing h1(j)
                const float* h0v = h0ring + (j & 1) * 512 + rb * 32;   // h0(j)
                const float* h1v = h1ring + ((j + 1) & 1) * 512 + rb * 32;  // h1(j-1)
                u64 cr[4], cz[4], cn[4], dr[4], dz[4], dn[4];
#pragma unroll
                for (int r = 0; r < 4; r++) {
                    cr[r] = pack2(biR, 0.f); cz[r] = pack2(biZ, 0.f); cn[r] = pack2(biN, 0.f);
                    dr[r] = pack2(bhR, 0.f); dz[r] = pack2(bhZ, 0.f); dn[r] = pack2(bhN, 0.f);
                }
#pragma unroll
                for (int kk = 0; kk < 8; kk++) {
                    ulonglong2 hr = *(const ulonglong2*)(w4hh1 + kk * 96 + lane);
                    ulonglong2 hz = *(const ulonglong2*)(w4hh1 + kk * 96 + 32 + lane);
                    ulonglong2 hn = *(const ulonglong2*)(w4hh1 + kk * 96 + 64 + lane);
#pragma unroll
                    for (int r = 0; r < 4; r++) {
                        ulonglong2 av = *(const ulonglong2*)(h0v + r * 32 + kk * 4);
                        ulonglong2 bv = *(const ulonglong2*)(h1v + r * 32 + kk * 4);
                        cr[r] = ffma2(iwr[2 * kk], av.x, cr[r]); cr[r] = ffma2(iwr[2 * kk + 1], av.y, cr[r]);
                        cz[r] = ffma2(iwz[2 * kk], av.x, cz[r]); cz[r] = ffma2(iwz[2 * kk + 1], av.y, cz[r]);
                        cn[r] = ffma2(iwn[2 * kk], av.x, cn[r]); cn[r] = ffma2(iwn[2 * kk + 1], av.y, cn[r]);
                        dr[r] = ffma2(hr.x, bv.x, dr[r]); dr[r] = ffma2(hr.y, bv.y, dr[r]);
                        dz[r] = ffma2(hz.x, bv.x, dz[r]); dz[r] = ffma2(hz.y, bv.y, dz[r]);
                        dn[r] = ffma2(hn.x, bv.x, dn[r]); dn[r] = ffma2(hn.y, bv.y, dn[r]);
                    }
                }
                float* hw = h1ring + (j & 1) * 512 + rb * 32;
#pragma unroll
                for (int r = 0; r < 4; r++) {
                    float rg = fast_sigmoid(sum2(cr[r]) + sum2(dr[r]));
                    float zg = fast_sigmoid(sum2(cz[r]) + sum2(dz[r]));
                    float ng = fast_tanh(sum2(cn[r]) + rg * sum2(dn[r]));
                    h1r[r] = ng + zg * (h1r[r] - ng);
                    hw[r * 32 + lane] = h1r[r];
                }
            }
            BAR();
        }
        // outputs: h_last1 + classifier y
#pragma unroll
        for (int r = 0; r < 4; r++) {
            int row = rowbase16 + rb + r;
            out[BB + BB * HH + row * HH + lane] = h1r[r];
            float p = h1r[r] * wc;
#pragma unroll
            for (int off = 16; off; off >>= 1) p += __shfl_xor_sync(0xffffffffu, p, off);
            if (lane == 0) out[row] = fast_sigmoid(p + bc);
        }

    } else {
        // ============ producer warps: gx(t) = W_ih0·x(t) + b_ih0, one step ahead ============
        const int p  = warp - 8;
        const int rg = (p & 1) * 8;          // 8-row group
        const int kh = p >> 1;               // K-half of D=64
        u64 pr[16], pz[16], pn[16];
#pragma unroll
        for (int i = 0; i < 8; i++) {
            ulonglong2 a = *(const ulonglong2*)(wih0 + lane * 64        + kh * 32 + i * 4);
            ulonglong2 b = *(const ulonglong2*)(wih0 + (32 + lane) * 64 + kh * 32 + i * 4);
            ulonglong2 c = *(const ulonglong2*)(wih0 + (64 + lane) * 64 + kh * 32 + i * 4);
            pr[2 * i] = a.x; pr[2 * i + 1] = a.y;
            pz[2 * i] = b.x; pz[2 * i + 1] = b.y;
            pn[2 * i] = c.x; pn[2 * i + 1] = c.y;
        }
        float bR = 0.f, bZ = 0.f, bN = 0.f;
        if (kh == 0) { bR = bih0[lane]; bZ = bih0[32 + lane]; bN = bih0[64 + lane]; }

        float4* xsw = xs + p * 64;
        const int s0 = lane, s1 = lane + 32;
        const float4* xg0 = (const float4*)(x + (size_t)(rowbase16 + rg + (s0 >> 3)) * TT * DD + kh * 32) + (s0 & 7);
        const float4* xg1 = (const float4*)(x + (size_t)(rowbase16 + rg + (s1 >> 3)) * TT * DD + kh * 32) + (s1 & 7);
        float4* xst0 = xsw + s0;
        float4* xst1 = xsw + s1;

        // prologue: gx(0) into slot 0
        float4 xb0 = *xg0, xb1 = *xg1; xg0 += 16; xg1 += 16;
        *xst0 = xb0; *xst1 = xb1;
        __syncwarp();
        xb0 = *xg0; xb1 = *xg1; xg0 += 16; xg1 += 16;   // prefetch x(1)
        gx_gemm(pr, pz, pn, xsw, gxs + kh * 1536 + rg * 96, lane, bR, bZ, bN);

        BAR();

        for (int i = 0; i <= TT; i++) {
            if (i + 1 < TT) {
                *xst0 = xb0; *xst1 = xb1;
                __syncwarp();
                if (i + 2 < TT) { xb0 = *xg0; xb1 = *xg1; xg0 += 16; xg1 += 16; }
                gx_gemm(pr, pz, pn, xsw,
                        gxs + ((i + 1) & 1) * 3072 + kh * 1536 + rg * 96,
                        lane, bR, bZ, bN);
            }
            BAR();
        }
    }
}

extern "C" void kernel_launch(void* const* d_in, const int* in_sizes, int n_in,
                              void* d_out, int out_size) {
    (void)in_sizes; (void)n_in; (void)out_size;
    const float* x    = (const float*)d_in[0];
    const float* wih0 = (const float*)d_in[1];
    const float* whh0 = (const float*)d_in[2];
    const float* bih0 = (const float*)d_in[3];
    const float* bhh0 = (const float*)d_in[4];
    const float* wih1 = (const float*)d_in[5];
    const float* whh1 = (const float*)d_in[6];
    const float* bih1 = (const float*)d_in[7];
    const float* bhh1 = (const float*)d_in[8];
    const float* wcls = (const float*)d_in[9];
    const float* bcls = (const float*)d_in[10];
    float* out = (float*)d_out;

    const int smem_bytes = 49152;   // 12KB w4hh1 + 24KB gxs + 4KB h0 + 4KB h1 + 4KB xs + pad
    cudaFuncSetAttribute(gru2_kernel, cudaFuncAttributeMaxDynamicSharedMemorySize, smem_bytes);
    gru2_kernel<<<128, 384, smem_bytes>>>(x, wih0, whh0, bih0, bhh0,
                                          wih1, whh1, bih1, bhh1, wcls, bcls, out);
}

// round 10
// speedup vs baseline: 1.2460x; 1.1510x over previous
#include <cuda_runtime.h>
#include <cstddef>

#define BB 2048
#define TT 1024
#define DD 64
#define HH 32
#define CH 8
#define NCH 128

typedef unsigned long long u64;

// ---- packed fp32x2 helpers (sm_100+) ----
__device__ __forceinline__ u64 ffma2(u64 a, u64 b, u64 c) {
    u64 d;
    asm("fma.rn.f32x2 %0, %1, %2, %3;" : "=l"(d) : "l"(a), "l"(b), "l"(c));
    return d;
}
__device__ __forceinline__ u64 pack2(float lo, float hi) {
    u64 r;
    asm("mov.b64 %0, {%1, %2};" : "=l"(r) : "f"(lo), "f"(hi));
    return r;
}
__device__ __forceinline__ float sum2(u64 v) {
    float a, b;
    asm("mov.b64 {%0, %1}, %2;" : "=f"(a), "=f"(b) : "l"(v));
    return a + b;
}
__device__ __forceinline__ float fast_sigmoid(float x) {
    float e;
    asm("ex2.approx.f32 %0, %1;" : "=f"(e) : "f"(-1.4426950408889634f * x));
    float r;
    asm("rcp.approx.f32 %0, %1;" : "=f"(r) : "f"(1.0f + e));
    return r;
}
__device__ __forceinline__ float fast_tanh(float x) {
    return fmaf(2.0f, fast_sigmoid(2.0f * x), -1.0f);
}

#define BAR() asm volatile("bar.sync 0, 384;" ::: "memory")

// Producer: stage x rows rb..rb+3 for chunk k, then gx = W_ih0·x + b (full K=64)
__device__ __forceinline__ void produce_chunk(
    const float* __restrict__ x, const float4* __restrict__ w4ih0,
    float* __restrict__ gxs, float* __restrict__ xst,
    int rowbase16, int rb, int k, int lane,
    float bR, float bZ, float bN)
{
    // stage: 4 rows x 8 steps x 64 floats = 512 float4, 16 per lane
#pragma unroll
    for (int i = 0; i < 16; i++) {
        int f   = i * 32 + lane;       // float4 index within 512
        int rl  = f >> 7;              // local row 0..3
        int rem = f & 127;             // within row: 8 steps x 16 f4, contiguous in gmem
        float4 v = *((const float4*)(x + (size_t)(rowbase16 + rb + rl) * TT * DD
                                        + (size_t)(k * CH) * DD) + rem);
        *((float4*)(xst + (rb + rl) * 512) + rem) = v;
    }
    __syncwarp();

    float* gbase = gxs + (k & 1) * 12288;
#pragma unroll 1
    for (int r = 0; r < 4; r++) {
        const float* xrow = xst + (rb + r) * 512;
        u64 a0[8], a1[8], a2[8];
#pragma unroll
        for (int t = 0; t < 8; t++) {
            a0[t] = pack2(bR, 0.f); a1[t] = pack2(bZ, 0.f); a2[t] = pack2(bN, 0.f);
        }
#pragma unroll 4
        for (int kk = 0; kk < 16; kk++) {
            ulonglong2 wr = *(const ulonglong2*)(w4ih0 + kk * 96 + lane);
            ulonglong2 wz = *(const ulonglong2*)(w4ih0 + kk * 96 + 32 + lane);
            ulonglong2 wn = *(const ulonglong2*)(w4ih0 + kk * 96 + 64 + lane);
#pragma unroll
            for (int t = 0; t < 8; t++) {
                ulonglong2 xv = *(const ulonglong2*)(xrow + t * 64 + kk * 4);
                a0[t] = ffma2(wr.x, xv.x, a0[t]); a0[t] = ffma2(wr.y, xv.y, a0[t]);
                a1[t] = ffma2(wz.x, xv.x, a1[t]); a1[t] = ffma2(wz.y, xv.y, a1[t]);
                a2[t] = ffma2(wn.x, xv.x, a2[t]); a2[t] = ffma2(wn.y, xv.y, a2[t]);
            }
        }
#pragma unroll
        for (int t = 0; t < 8; t++) {
            float* o = gbase + t * 1536 + (rb + r) * 96;
            o[lane]      = sum2(a0[t]);
            o[32 + lane] = sum2(a1[t]);
            o[64 + lane] = sum2(a2[t]);
        }
    }
}

__global__ void __launch_bounds__(384, 1)
gru2_kernel(const float* __restrict__ x,
            const float* __restrict__ wih0, const float* __restrict__ whh0,
            const float* __restrict__ bih0, const float* __restrict__ bhh0,
            const float* __restrict__ wih1, const float* __restrict__ whh1,
            const float* __restrict__ bih1, const float* __restrict__ bhh1,
            const float* __restrict__ wcls, const float* __restrict__ bcls,
            float* __restrict__ out)
{
    extern __shared__ float smf[];
    float4* w4ih0 = (float4*)smf;            // [16][96] f4 : floats 0..6143
    float4* w4hh1 = (float4*)(smf + 6144);   // [8][96]  f4 : 6144..9215
    float*  gxs   = smf + 9216;              // [2][8][16][96] : 24576 floats
    float*  h0rg  = smf + 33792;             // [2][8][16][32] : 8192
    float*  h1bf  = smf + 41984;             // [2][16][32]    : 1024
    float*  xst   = smf + 43008;             // [16][8][64]    : 8192  (total 51200 f)

    const int tid  = threadIdx.x;
    const int warp = tid >> 5;
    const int lane = tid & 31;
    const int rowbase16 = blockIdx.x * 16;

    // cooperative init
    for (int idx = tid; idx < 1536; idx += 384) {
        int g = idx % 96, kk = idx / 96;
        w4ih0[kk * 96 + g] = *(const float4*)(wih0 + g * 64 + kk * 4);
    }
    for (int idx = tid; idx < 768; idx += 384) {
        int g = idx % 96, kk = idx / 96;
        w4hh1[kk * 96 + g] = *(const float4*)(whh1 + g * 32 + kk * 4);
    }
    for (int i = tid; i < 9216; i += 384) h0rg[i] = 0.f;   // h0 ring + h1bf contiguous
    __syncthreads();

    if (warp < 4) {
        // ================= L0: h0 recurrence, 4 rows, W_hh0 in registers =================
        u64 wr[16], wz[16], wn[16];
#pragma unroll
        for (int i = 0; i < 8; i++) {
            ulonglong2 a = *(const ulonglong2*)(whh0 + lane * 32 + i * 4);
            ulonglong2 b = *(const ulonglong2*)(whh0 + (32 + lane) * 32 + i * 4);
            ulonglong2 c = *(const ulonglong2*)(whh0 + (64 + lane) * 32 + i * 4);
            wr[2 * i] = a.x; wr[2 * i + 1] = a.y;
            wz[2 * i] = b.x; wz[2 * i + 1] = b.y;
            wn[2 * i] = c.x; wn[2 * i + 1] = c.y;
        }
        const float bR = bhh0[lane], bZ = bhh0[32 + lane], bN = bhh0[64 + lane];
        const int rb = warp * 4;
        float h0r[4] = {0.f, 0.f, 0.f, 0.f};

        BAR();   // matches producer prologue

        for (int it = 0; it <= NCH; it++) {
            if (it < NCH) {
                const int slot = it & 1;
                const float* gch = gxs + slot * 12288;
                float* hch = h0rg + slot * 4096;
                const float* hprev0 = h0rg + (slot ^ 1) * 4096 + 7 * 512;
#pragma unroll 2
                for (int tt = 0; tt < CH; tt++) {
                    const float* hp = (tt == 0) ? hprev0 : (hch + (tt - 1) * 512);
                    u64 gr[4], gz[4], gn[4];
#pragma unroll
                    for (int r = 0; r < 4; r++) {
                        gr[r] = pack2(bR, 0.f); gz[r] = pack2(bZ, 0.f); gn[r] = pack2(bN, 0.f);
                    }
#pragma unroll
                    for (int kk = 0; kk < 8; kk++) {
#pragma unroll
                        for (int r = 0; r < 4; r++) {
                            ulonglong2 hv = *(const ulonglong2*)(hp + (rb + r) * 32 + kk * 4);
                            gr[r] = ffma2(wr[2 * kk], hv.x, gr[r]); gr[r] = ffma2(wr[2 * kk + 1], hv.y, gr[r]);
                            gz[r] = ffma2(wz[2 * kk], hv.x, gz[r]); gz[r] = ffma2(wz[2 * kk + 1], hv.y, gz[r]);
                            gn[r] = ffma2(wn[2 * kk], hv.x, gn[r]); gn[r] = ffma2(wn[2 * kk + 1], hv.y, gn[r]);
                        }
                    }
                    const float* g = gch + tt * 1536;
                    float* hw = hch + tt * 512;
#pragma unroll
                    for (int r = 0; r < 4; r++) {
                        const float* gg = g + (rb + r) * 96;
                        float rgate = fast_sigmoid(gg[lane] + sum2(gr[r]));
                        float zgate = fast_sigmoid(gg[32 + lane] + sum2(gz[r]));
                        float ngate = fast_tanh(gg[64 + lane] + rgate * sum2(gn[r]));  // torch GRU
                        h0r[r] = ngate + zgate * (h0r[r] - ngate);
                        hw[(rb + r) * 32 + lane] = h0r[r];
                    }
                    __syncwarp();
                }
            }
            BAR();
        }
#pragma unroll
        for (int r = 0; r < 4; r++)
            out[BB + (rowbase16 + rb + r) * HH + lane] = h0r[r];

    } else if (warp < 8) {
        // ================= L1: h1 recurrence one chunk behind, W_ih1 in registers =================
        u64 iwr[16], iwz[16], iwn[16];
#pragma unroll
        for (int i = 0; i < 8; i++) {
            ulonglong2 a = *(const ulonglong2*)(wih1 + lane * 32 + i * 4);
            ulonglong2 b = *(const ulonglong2*)(wih1 + (32 + lane) * 32 + i * 4);
            ulonglong2 c = *(const ulonglong2*)(wih1 + (64 + lane) * 32 + i * 4);
            iwr[2 * i] = a.x; iwr[2 * i + 1] = a.y;
            iwz[2 * i] = b.x; iwz[2 * i + 1] = b.y;
            iwn[2 * i] = c.x; iwn[2 * i + 1] = c.y;
        }
        const float biR = bih1[lane], biZ = bih1[32 + lane], biN = bih1[64 + lane];
        const float bhR = bhh1[lane], bhZ = bhh1[32 + lane], bhN = bhh1[64 + lane];
        const float wc = wcls[lane];
        const float bc = bcls[0];
        const int rb = (warp - 4) * 4;
        float h1r[4] = {0.f, 0.f, 0.f, 0.f};

        BAR();

        for (int it = 0; it <= NCH; it++) {
            if (it >= 1) {
                const int jslot = (it - 1) & 1;
                const float* h0ch = h0rg + jslot * 4096;
#pragma unroll 2
                for (int tt = 0; tt < CH; tt++) {
                    // pass 1: W_hh1 · h1(t-1)  (shared weights, accums collapsed to scalars)
                    // h1 double buffer: PREVIOUS slot is ((tt+1)&1), current write is (tt&1).
                    const float* h1p = h1bf + ((tt + 1) & 1) * 512;
                    u64 dr[4], dz[4], dn[4];
#pragma unroll
                    for (int r = 0; r < 4; r++) {
                        dr[r] = pack2(bhR, 0.f); dz[r] = pack2(bhZ, 0.f); dn[r] = pack2(bhN, 0.f);
                    }
#pragma unroll
                    for (int kk = 0; kk < 8; kk++) {
                        ulonglong2 hr = *(const ulonglong2*)(w4hh1 + kk * 96 + lane);
                        ulonglong2 hz = *(const ulonglong2*)(w4hh1 + kk * 96 + 32 + lane);
                        ulonglong2 hn = *(const ulonglong2*)(w4hh1 + kk * 96 + 64 + lane);
#pragma unroll
                        for (int r = 0; r < 4; r++) {
                            ulonglong2 hv = *(const ulonglong2*)(h1p + (rb + r) * 32 + kk * 4);
                            dr[r] = ffma2(hr.x, hv.x, dr[r]); dr[r] = ffma2(hr.y, hv.y, dr[r]);
                            dz[r] = ffma2(hz.x, hv.x, dz[r]); dz[r] = ffma2(hz.y, hv.y, dz[r]);
                            dn[r] = ffma2(hn.x, hv.x, dn[r]); dn[r] = ffma2(hn.y, hv.y, dn[r]);
                        }
                    }
                    float sr[4], sz[4], sn[4];
#pragma unroll
                    for (int r = 0; r < 4; r++) { sr[r] = sum2(dr[r]); sz[r] = sum2(dz[r]); sn[r] = sum2(dn[r]); }

                    // pass 2: W_ih1 · h0(t)  (register weights)
                    const float* h0p = h0ch + tt * 512;
                    u64 cr[4], cz[4], cn[4];
#pragma unroll
                    for (int r = 0; r < 4; r++) {
                        cr[r] = pack2(biR, 0.f); cz[r] = pack2(biZ, 0.f); cn[r] = pack2(biN, 0.f);
                    }
#pragma unroll
                    for (int kk = 0; kk < 8; kk++) {
#pragma unroll
                        for (int r = 0; r < 4; r++) {
                            ulonglong2 av = *(const ulonglong2*)(h0p + (rb + r) * 32 + kk * 4);
                            cr[r] = ffma2(iwr[2 * kk], av.x, cr[r]); cr[r] = ffma2(iwr[2 * kk + 1], av.y, cr[r]);
                            cz[r] = ffma2(iwz[2 * kk], av.x, cz[r]); cz[r] = ffma2(iwz[2 * kk + 1], av.y, cz[r]);
                            cn[r] = ffma2(iwn[2 * kk], av.x, cn[r]); cn[r] = ffma2(iwn[2 * kk + 1], av.y, cn[r]);
                        }
                    }
                    float* hw = h1bf + (tt & 1) * 512;
#pragma unroll
                    for (int r = 0; r < 4; r++) {
                        float rg = fast_sigmoid(sum2(cr[r]) + sr[r]);
                        float zg = fast_sigmoid(sum2(cz[r]) + sz[r]);
                        float ng = fast_tanh(sum2(cn[r]) + rg * sn[r]);
                        h1r[r] = ng + zg * (h1r[r] - ng);
                        hw[(rb + r) * 32 + lane] = h1r[r];
                    }
                    __syncwarp();
                }
            }
            BAR();
        }
        // outputs: h_last1 + classifier y
#pragma unroll
        for (int r = 0; r < 4; r++) {
            int row = rowbase16 + rb + r;
            out[BB + BB * HH + row * HH + lane] = h1r[r];
            float p = h1r[r] * wc;
#pragma unroll
            for (int off = 16; off; off >>= 1) p += __shfl_xor_sync(0xffffffffu, p, off);
            if (lane == 0) out[row] = fast_sigmoid(p + bc);
        }

    } else {
        // ================= producers: gx one chunk ahead (shared weights) =================
        const int p  = warp - 8;
        const int rb = p * 4;
        float bR = bih0[lane], bZ = bih0[32 + lane], bN = bih0[64 + lane];

        // prologue: chunk 0
        produce_chunk(x, w4ih0, gxs, xst, rowbase16, rb, 0, lane, bR, bZ, bN);
        BAR();

        for (int it = 0; it <= NCH; it++) {
            if (it + 1 < NCH) {
                produce_chunk(x, w4ih0, gxs, xst, rowbase16, rb, it + 1, lane, bR, bZ, bN);
            }
            BAR();
        }
    }
}

extern "C" void kernel_launch(void* const* d_in, const int* in_sizes, int n_in,
                              void* d_out, int out_size) {
    (void)in_sizes; (void)n_in; (void)out_size;
    const float* x    = (const float*)d_in[0];
    const float* wih0 = (const float*)d_in[1];
    const float* whh0 = (const float*)d_in[2];
    const float* bih0 = (const float*)d_in[3];
    const float* bhh0 = (const float*)d_in[4];
    const float* wih1 = (const float*)d_in[5];
    const float* whh1 = (const float*)d_in[6];
    const float* bih1 = (const float*)d_in[7];
    const float* bhh1 = (const float*)d_in[8];
    const float* wcls = (const float*)d_in[9];
    const float* bcls = (const float*)d_in[10];
    float* out = (float*)d_out;

    const int smem_bytes = 204800;   // 51200 floats (see layout comment)
    cudaFuncSetAttribute(gru2_kernel, cudaFuncAttributeMaxDynamicSharedMemorySize, smem_bytes);
    gru2_kernel<<<128, 384, smem_bytes>>>(x, wih0, whh0, bih0, bhh0,
                                          wih1, whh1, bih1, bhh1, wcls, bcls, out);
}

// round 11
// speedup vs baseline: 1.2460x; 1.0001x over previous
#include <cuda_runtime.h>
#include <cstddef>

#define BB 2048
#define TT 1024
#define DD 64
#define HH 32

typedef unsigned long long u64;

// scratch: gate preactivations [row][t][96] (reused by phase C), and all h0 [row][t][32]
__device__ float g_gx[(size_t)BB * TT * 96];
__device__ float g_h0[(size_t)BB * TT * 32];

__device__ __forceinline__ u64 ffma2(u64 a, u64 b, u64 c) {
    u64 d;
    asm("fma.rn.f32x2 %0, %1, %2, %3;" : "=l"(d) : "l"(a), "l"(b), "l"(c));
    return d;
}
__device__ __forceinline__ u64 pack2(float lo, float hi) {
    u64 r;
    asm("mov.b64 %0, {%1, %2};" : "=l"(r) : "f"(lo), "f"(hi));
    return r;
}
__device__ __forceinline__ float sum2(u64 v) {
    float a, b;
    asm("mov.b64 {%0, %1}, %2;" : "=f"(a), "=f"(b) : "l"(v));
    return a + b;
}
__device__ __forceinline__ float fast_sigmoid(float x) {
    float e;
    asm("ex2.approx.f32 %0, %1;" : "=f"(e) : "f"(-1.4426950408889634f * x));
    float r;
    asm("rcp.approx.f32 %0, %1;" : "=f"(r) : "f"(1.0f + e));
    return r;
}
__device__ __forceinline__ float fast_tanh(float x) {
    return fmaf(2.0f, fast_sigmoid(2.0f * x), -1.0f);
}

// ================= Phase A: gx0 = x @ W_ih0^T + b_ih0  (K=64) =================
// One block per row; 8 warps x 128 tokens; warp-private staging, no block syncs in loop.
__global__ void __launch_bounds__(256, 1)
gx0_kernel(const float* __restrict__ x,
           const float* __restrict__ wih0, const float* __restrict__ bih0)
{
    __shared__ float4 w4[16 * 96];     // 24KB: [kk][gate] transposed
    __shared__ float4 xs[8 * 128];     // 16KB: per-warp 8 tokens x 16 f4

    const int tid = threadIdx.x, warp = tid >> 5, lane = tid & 31;
    for (int i = tid; i < 1536; i += 256) {
        int g = i % 96, kk = i / 96;
        w4[kk * 96 + g] = *(const float4*)(wih0 + g * 64 + kk * 4);
    }
    __syncthreads();
    const float b0 = bih0[lane], b1 = bih0[32 + lane], b2 = bih0[64 + lane];

    const int row = blockIdx.x;
    const float4* xg = (const float4*)(x + (size_t)row * TT * DD) + warp * 2048;
    float* gw = g_gx + ((size_t)row * TT + warp * 128) * 96;
    float4* xsw = xs + warp * 128;

    float4 xb[4];
#pragma unroll
    for (int i = 0; i < 4; i++) xb[i] = xg[i * 32 + lane];
    xg += 128;

    for (int it = 0; it < 16; it++) {
#pragma unroll
        for (int i = 0; i < 4; i++) xsw[i * 32 + lane] = xb[i];
        __syncwarp();
        if (it + 1 < 16) {
#pragma unroll
            for (int i = 0; i < 4; i++) xb[i] = xg[i * 32 + lane];
            xg += 128;
        }
        u64 a0[8], a1[8], a2[8];
#pragma unroll
        for (int t = 0; t < 8; t++) {
            a0[t] = pack2(b0, 0.f); a1[t] = pack2(b1, 0.f); a2[t] = pack2(b2, 0.f);
        }
#pragma unroll 4
        for (int kk = 0; kk < 16; kk++) {
            ulonglong2 wr = *(const ulonglong2*)(w4 + kk * 96 + lane);
            ulonglong2 wz = *(const ulonglong2*)(w4 + kk * 96 + 32 + lane);
            ulonglong2 wn = *(const ulonglong2*)(w4 + kk * 96 + 64 + lane);
#pragma unroll
            for (int t = 0; t < 8; t++) {
                ulonglong2 xv = *(const ulonglong2*)(xsw + t * 16 + kk);
                a0[t] = ffma2(wr.x, xv.x, a0[t]); a0[t] = ffma2(wr.y, xv.y, a0[t]);
                a1[t] = ffma2(wz.x, xv.x, a1[t]); a1[t] = ffma2(wz.y, xv.y, a1[t]);
                a2[t] = ffma2(wn.x, xv.x, a2[t]); a2[t] = ffma2(wn.y, xv.y, a2[t]);
            }
        }
#pragma unroll
        for (int t = 0; t < 8; t++) {
            float* o = gw + (it * 8 + t) * 96;
            o[lane] = sum2(a0[t]); o[32 + lane] = sum2(a1[t]); o[64 + lane] = sum2(a2[t]);
        }
        __syncwarp();
    }
}

// ================= Phase C: gxl1 = h0_all @ W_ih1^T + b_ih1  (K=32) =================
__global__ void __launch_bounds__(256, 1)
gxl1_kernel(const float* __restrict__ wih1, const float* __restrict__ bih1)
{
    __shared__ float4 w4[8 * 96];      // 12KB
    __shared__ float4 hs[8 * 64];      // 8KB: per-warp 8 tokens x 8 f4

    const int tid = threadIdx.x, warp = tid >> 5, lane = tid & 31;
    for (int i = tid; i < 768; i += 256) {
        int g = i % 96, kk = i / 96;
        w4[kk * 96 + g] = *(const float4*)(wih1 + g * 32 + kk * 4);
    }
    __syncthreads();
    const float b0 = bih1[lane], b1 = bih1[32 + lane], b2 = bih1[64 + lane];

    const int row = blockIdx.x;
    const float4* hg = (const float4*)(g_h0 + (size_t)row * TT * 32) + warp * 1024;
    float* gw = g_gx + ((size_t)row * TT + warp * 128) * 96;
    float4* hsw = hs + warp * 64;

    float4 hb[2];
#pragma unroll
    for (int i = 0; i < 2; i++) hb[i] = hg[i * 32 + lane];
    hg += 64;

    for (int it = 0; it < 16; it++) {
#pragma unroll
        for (int i = 0; i < 2; i++) hsw[i * 32 + lane] = hb[i];
        __syncwarp();
        if (it + 1 < 16) {
#pragma unroll
            for (int i = 0; i < 2; i++) hb[i] = hg[i * 32 + lane];
            hg += 64;
        }
        u64 a0[8], a1[8], a2[8];
#pragma unroll
        for (int t = 0; t < 8; t++) {
            a0[t] = pack2(b0, 0.f); a1[t] = pack2(b1, 0.f); a2[t] = pack2(b2, 0.f);
        }
#pragma unroll 4
        for (int kk = 0; kk < 8; kk++) {
            ulonglong2 wr = *(const ulonglong2*)(w4 + kk * 96 + lane);
            ulonglong2 wz = *(const ulonglong2*)(w4 + kk * 96 + 32 + lane);
            ulonglong2 wn = *(const ulonglong2*)(w4 + kk * 96 + 64 + lane);
#pragma unroll
            for (int t = 0; t < 8; t++) {
                ulonglong2 hv = *(const ulonglong2*)(hsw + t * 8 + kk);
                a0[t] = ffma2(wr.x, hv.x, a0[t]); a0[t] = ffma2(wr.y, hv.y, a0[t]);
                a1[t] = ffma2(wz.x, hv.x, a1[t]); a1[t] = ffma2(wz.y, hv.y, a1[t]);
                a2[t] = ffma2(wn.x, hv.x, a2[t]); a2[t] = ffma2(wn.y, hv.y, a2[t]);
            }
        }
#pragma unroll
        for (int t = 0; t < 8; t++) {
            float* o = gw + (it * 8 + t) * 96;
            o[lane] = sum2(a0[t]); o[32 + lane] = sum2(a1[t]); o[64 + lane] = sum2(a2[t]);
        }
        __syncwarp();
    }
}

// ================= Phase B: layer-0 recurrence only =================
// 128 blocks x 8 warps x 2 rows/warp; W_hh0 in regs; gx via 2-step reg prefetch.
__global__ void __launch_bounds__(256, 1)
rec0_kernel(const float* __restrict__ whh0, const float* __restrict__ bhh0,
            float* __restrict__ out)
{
    __shared__ float hs[512];
    const int tid = threadIdx.x, warp = tid >> 5, lane = tid & 31;
    const int r0 = blockIdx.x * 16 + warp * 2;

    u64 wr[16], wz[16], wn[16];
#pragma unroll
    for (int i = 0; i < 8; i++) {
        ulonglong2 a = *(const ulonglong2*)(whh0 + lane * 32 + i * 4);
        ulonglong2 b = *(const ulonglong2*)(whh0 + (32 + lane) * 32 + i * 4);
        ulonglong2 c = *(const ulonglong2*)(whh0 + (64 + lane) * 32 + i * 4);
        wr[2 * i] = a.x; wr[2 * i + 1] = a.y;
        wz[2 * i] = b.x; wz[2 * i + 1] = b.y;
        wn[2 * i] = c.x; wn[2 * i + 1] = c.y;
    }
    const float bR = bhh0[lane], bZ = bhh0[32 + lane], bN = bhh0[64 + lane];

    float* hw = hs + warp * 64;
    hw[lane] = 0.f; hw[32 + lane] = 0.f;
    float ha = 0.f, hb = 0.f;

    const float* ga = g_gx + (size_t)r0 * TT * 96;
    const float* gb = ga + (size_t)TT * 96;
    float* hoA = g_h0 + (size_t)r0 * TT * 32;
    float* hoB = hoA + (size_t)TT * 32;

    // 2-deep prefetch (indices static via unroll 2)
    float fa0[3], fa1[3], fb0[3], fb1[3];
    fa0[0] = ga[lane]; fa0[1] = ga[32 + lane]; fa0[2] = ga[64 + lane]; ga += 96;
    fb0[0] = gb[lane]; fb0[1] = gb[32 + lane]; fb0[2] = gb[64 + lane]; gb += 96;
    fa1[0] = ga[lane]; fa1[1] = ga[32 + lane]; fa1[2] = ga[64 + lane]; ga += 96;
    fb1[0] = gb[lane]; fb1[1] = gb[32 + lane]; fb1[2] = gb[64 + lane]; gb += 96;
    __syncwarp();

#pragma unroll 2
    for (int t = 0; t < TT; t++) {
        float xra, xza, xna, xrb, xzb, xnb;
        if ((t & 1) == 0) { xra = fa0[0]; xza = fa0[1]; xna = fa0[2]; xrb = fb0[0]; xzb = fb0[1]; xnb = fb0[2]; }
        else              { xra = fa1[0]; xza = fa1[1]; xna = fa1[2]; xrb = fb1[0]; xzb = fb1[1]; xnb = fb1[2]; }
        if (t + 2 < TT) {
            if ((t & 1) == 0) {
                fa0[0] = ga[lane]; fa0[1] = ga[32 + lane]; fa0[2] = ga[64 + lane];
                fb0[0] = gb[lane]; fb0[1] = gb[32 + lane]; fb0[2] = gb[64 + lane];
            } else {
                fa1[0] = ga[lane]; fa1[1] = ga[32 + lane]; fa1[2] = ga[64 + lane];
                fb1[0] = gb[lane]; fb1[1] = gb[32 + lane]; fb1[2] = gb[64 + lane];
            }
            ga += 96; gb += 96;
        }

        u64 gra = pack2(xra + bR, 0.f), gza = pack2(xza + bZ, 0.f), gna = pack2(bN, 0.f);
        u64 grb = pack2(xrb + bR, 0.f), gzb = pack2(xzb + bZ, 0.f), gnb = pack2(bN, 0.f);
#pragma unroll
        for (int kk = 0; kk < 8; kk++) {
            ulonglong2 va = *(const ulonglong2*)(hw + kk * 4);
            ulonglong2 vb = *(const ulonglong2*)(hw + 32 + kk * 4);
            gra = ffma2(wr[2 * kk], va.x, gra); gra = ffma2(wr[2 * kk + 1], va.y, gra);
            gza = ffma2(wz[2 * kk], va.x, gza); gza = ffma2(wz[2 * kk + 1], va.y, gza);
            gna = ffma2(wn[2 * kk], va.x, gna); gna = ffma2(wn[2 * kk + 1], va.y, gna);
            grb = ffma2(wr[2 * kk], vb.x, grb); grb = ffma2(wr[2 * kk + 1], vb.y, grb);
            gzb = ffma2(wz[2 * kk], vb.x, gzb); gzb = ffma2(wz[2 * kk + 1], vb.y, gzb);
            gnb = ffma2(wn[2 * kk], vb.x, gnb); gnb = ffma2(wn[2 * kk + 1], vb.y, gnb);
        }
        {
            float r = fast_sigmoid(sum2(gra));
            float z = fast_sigmoid(sum2(gza));
            float n = fast_tanh(xna + r * sum2(gna));   // b_hh_n inside r* (torch GRU)
            ha = n + z * (ha - n);
            float r2 = fast_sigmoid(sum2(grb));
            float z2 = fast_sigmoid(sum2(gzb));
            float n2 = fast_tanh(xnb + r2 * sum2(gnb));
            hb = n2 + z2 * (hb - n2);
        }
        hoA[t * 32 + lane] = ha;
        hoB[t * 32 + lane] = hb;
        __syncwarp();
        hw[lane] = ha; hw[32 + lane] = hb;
        __syncwarp();
    }
    out[BB + r0 * HH + lane]       = ha;   // h_last0
    out[BB + (r0 + 1) * HH + lane] = hb;
}

// ================= Phase D: layer-1 recurrence only + classifier =================
__global__ void __launch_bounds__(256, 1)
rec1_kernel(const float* __restrict__ whh1, const float* __restrict__ bhh1,
            const float* __restrict__ wcls, const float* __restrict__ bcls,
            float* __restrict__ out)
{
    __shared__ float hs[512];
    const int tid = threadIdx.x, warp = tid >> 5, lane = tid & 31;
    const int r0 = blockIdx.x * 16 + warp * 2;

    u64 wr[16], wz[16], wn[16];
#pragma unroll
    for (int i = 0; i < 8; i++) {
        ulonglong2 a = *(const ulonglong2*)(whh1 + lane * 32 + i * 4);
        ulonglong2 b = *(const ulonglong2*)(whh1 + (32 + lane) * 32 + i * 4);
        ulonglong2 c = *(const ulonglong2*)(whh1 + (64 + lane) * 32 + i * 4);
        wr[2 * i] = a.x; wr[2 * i + 1] = a.y;
        wz[2 * i] = b.x; wz[2 * i + 1] = b.y;
        wn[2 * i] = c.x; wn[2 * i + 1] = c.y;
    }
    const float bR = bhh1[lane], bZ = bhh1[32 + lane], bN = bhh1[64 + lane];

    float* hw = hs + warp * 64;
    hw[lane] = 0.f; hw[32 + lane] = 0.f;
    float ha = 0.f, hb = 0.f;

    const float* ga = g_gx + (size_t)r0 * TT * 96;   // now holds gxl1
    const float* gb = ga + (size_t)TT * 96;

    float fa0[3], fa1[3], fb0[3], fb1[3];
    fa0[0] = ga[lane]; fa0[1] = ga[32 + lane]; fa0[2] = ga[64 + lane]; ga += 96;
    fb0[0] = gb[lane]; fb0[1] = gb[32 + lane]; fb0[2] = gb[64 + lane]; gb += 96;
    fa1[0] = ga[lane]; fa1[1] = ga[32 + lane]; fa1[2] = ga[64 + lane]; ga += 96;
    fb1[0] = gb[lane]; fb1[1] = gb[32 + lane]; fb1[2] = gb[64 + lane]; gb += 96;
    __syncwarp();

#pragma unroll 2
    for (int t = 0; t < TT; t++) {
        float xra, xza, xna, xrb, xzb, xnb;
        if ((t & 1) == 0) { xra = fa0[0]; xza = fa0[1]; xna = fa0[2]; xrb = fb0[0]; xzb = fb0[1]; xnb = fb0[2]; }
        else              { xra = fa1[0]; xza = fa1[1]; xna = fa1[2]; xrb = fb1[0]; xzb = fb1[1]; xnb = fb1[2]; }
        if (t + 2 < TT) {
            if ((t & 1) == 0) {
                fa0[0] = ga[lane]; fa0[1] = ga[32 + lane]; fa0[2] = ga[64 + lane];
                fb0[0] = gb[lane]; fb0[1] = gb[32 + lane]; fb0[2] = gb[64 + lane];
            } else {
                fa1[0] = ga[lane]; fa1[1] = ga[32 + lane]; fa1[2] = ga[64 + lane];
                fb1[0] = gb[lane]; fb1[1] = gb[32 + lane]; fb1[2] = gb[64 + lane];
            }
            ga += 96; gb += 96;
        }

        u64 gra = pack2(xra + bR, 0.f), gza = pack2(xza + bZ, 0.f), gna = pack2(bN, 0.f);
        u64 grb = pack2(xrb + bR, 0.f), gzb = pack2(xzb + bZ, 0.f), gnb = pack2(bN, 0.f);
#pragma unroll
        for (int kk = 0; kk < 8; kk++) {
            ulonglong2 va = *(const ulonglong2*)(hw + kk * 4);
            ulonglong2 vb = *(const ulonglong2*)(hw + 32 + kk * 4);
            gra = ffma2(wr[2 * kk], va.x, gra); gra = ffma2(wr[2 * kk + 1], va.y, gra);
            gza = ffma2(wz[2 * kk], va.x, gza); gza = ffma2(wz[2 * kk + 1], va.y, gza);
            gna = ffma2(wn[2 * kk], va.x, gna); gna = ffma2(wn[2 * kk + 1], va.y, gna);
            grb = ffma2(wr[2 * kk], vb.x, grb); grb = ffma2(wr[2 * kk + 1], vb.y, grb);
            gzb = ffma2(wz[2 * kk], vb.x, gzb); gzb = ffma2(wz[2 * kk + 1], vb.y, gzb);
            gnb = ffma2(wn[2 * kk], vb.x, gnb); gnb = ffma2(wn[2 * kk + 1], vb.y, gnb);
        }
        {
            float r = fast_sigmoid(sum2(gra));
            float z = fast_sigmoid(sum2(gza));
            float n = fast_tanh(xna + r * sum2(gna));
            ha = n + z * (ha - n);
            float r2 = fast_sigmoid(sum2(grb));
            float z2 = fast_sigmoid(sum2(gzb));
            float n2 = fast_tanh(xnb + r2 * sum2(gnb));
            hb = n2 + z2 * (hb - n2);
        }
        __syncwarp();
        hw[lane] = ha; hw[32 + lane] = hb;
        __syncwarp();
    }

    out[BB + BB * HH + r0 * HH + lane]       = ha;   // h_last1
    out[BB + BB * HH + (r0 + 1) * HH + lane] = hb;
    const float wc = wcls[lane];
    float pA = ha * wc, pB = hb * wc;
#pragma unroll
    for (int off = 16; off; off >>= 1) {
        pA += __shfl_xor_sync(0xffffffffu, pA, off);
        pB += __shfl_xor_sync(0xffffffffu, pB, off);
    }
    if (lane == 0) {
        float bc = bcls[0];
        out[r0]     = fast_sigmoid(pA + bc);
        out[r0 + 1] = fast_sigmoid(pB + bc);
    }
}

extern "C" void kernel_launch(void* const* d_in, const int* in_sizes, int n_in,
                              void* d_out, int out_size) {
    (void)in_sizes; (void)n_in; (void)out_size;
    const float* x    = (const float*)d_in[0];
    const float* wih0 = (const float*)d_in[1];
    const float* whh0 = (const float*)d_in[2];
    const float* bih0 = (const float*)d_in[3];
    const float* bhh0 = (const float*)d_in[4];
    const float* wih1 = (const float*)d_in[5];
    const float* whh1 = (const float*)d_in[6];
    const float* bih1 = (const float*)d_in[7];
    const float* bhh1 = (const float*)d_in[8];
    const float* wcls = (const float*)d_in[9];
    const float* bcls = (const float*)d_in[10];
    float* out = (float*)d_out;

    gx0_kernel<<<BB, 256>>>(x, wih0, bih0);
    rec0_kernel<<<128, 256>>>(whh0, bhh0, out);
    gxl1_kernel<<<BB, 256>>>(wih1, bih1);
    rec1_kernel<<<128, 256>>>(whh1, bhh1, wcls, bcls, out);
}